// round 15
// baseline (speedup 1.0000x reference)
#include <cuda_runtime.h>
#include <cuda_bf16.h>
#include <cuda_fp16.h>
#include <math.h>
#include <stdint.h>

// Problem dims
#define TT 128
#define BB 32
#define EE 512
#define HH 1024
#define VV 32000
#define GG (3 * HH)       // 3072
#define MM (TT * BB)      // 4096
#define NCTA 128

// ---------------- scratch (device globals) ----------------------------------
__device__ float g_gx[MM * GG];
__device__ __nv_bfloat16 g_hBh[2][BB * HH];    // ping-pong h, bf16 hi, blocked
__device__ __nv_bfloat16 g_hBl[2][BB * HH];    // bf16 lo
// tree barrier state: 8 group counters on distinct 128B lines + root + flag
__device__ unsigned g_grp[8 * 32];
__device__ unsigned g_root;
__device__ unsigned g_flag;
__device__ __nv_bfloat16 g_Xh[MM * EE];
__device__ __nv_bfloat16 g_Xl[MM * EE];
__device__ __nv_bfloat16 g_Wh[GG * EE];
__device__ __nv_bfloat16 g_Wl[GG * EE];
__device__ __half g_Fw[VV * HH];
__device__ __half g_Fa[MM * HH];

// ---------------- helpers ----------------------------------------------------
__device__ __forceinline__ uint32_t smem_u32(const void* p) {
    uint32_t a;
    asm("{ .reg .u64 t; cvta.to.shared.u64 t, %1; cvt.u32.u64 %0, t; }"
        : "=r"(a) : "l"(p));
    return a;
}
__device__ __forceinline__ unsigned ld_acq(unsigned* p) {
    unsigned v;
    asm volatile("ld.acquire.gpu.u32 %0, [%1];" : "=r"(v) : "l"(p) : "memory");
    return v;
}
__device__ __forceinline__ void mbar_init(uint32_t mbar, int cnt) {
    asm volatile("mbarrier.init.shared.b64 [%0], %1;" :: "r"(mbar), "r"(cnt) : "memory");
}
__device__ __forceinline__ void mbar_expect_tx(uint32_t mbar, uint32_t bytes) {
    asm volatile("mbarrier.arrive.expect_tx.shared.b64 _, [%0], %1;"
                 :: "r"(mbar), "r"(bytes) : "memory");
}
__device__ __forceinline__ void mbar_arrive(uint32_t mbar) {
    asm volatile("mbarrier.arrive.shared.b64 _, [%0];" :: "r"(mbar) : "memory");
}
__device__ __forceinline__ void bulk_cp(uint32_t dst, const void* src, uint32_t bytes,
                                        uint32_t mbar) {
    asm volatile(
        "cp.async.bulk.shared::cluster.global.mbarrier::complete_tx::bytes "
        "[%0], [%1], %2, [%3];"
        :: "r"(dst), "l"(src), "r"(bytes), "r"(mbar) : "memory");
}
__device__ __forceinline__ void mbar_wait(uint32_t mbar, int ph) {
    asm volatile(
        "{\n\t.reg .pred P1;\n"
        "WL%=:\n\t"
        "mbarrier.try_wait.parity.acquire.cta.shared::cta.b64 P1, [%0], %1, 0x989680;\n\t"
        "@P1 bra.uni WD%=;\n\t"
        "bra.uni WL%=;\n"
        "WD%=:\n\t}"
        :: "r"(mbar), "r"(ph) : "memory");
}
__device__ __forceinline__ void ldm_x4(uint32_t* r, uint32_t addr) {
    asm volatile("ldmatrix.sync.aligned.m8n8.x4.shared.b16 {%0,%1,%2,%3}, [%4];"
                 : "=r"(r[0]), "=r"(r[1]), "=r"(r[2]), "=r"(r[3]) : "r"(addr));
}
__device__ __forceinline__ void ldm_x2(uint32_t* r, uint32_t addr) {
    asm volatile("ldmatrix.sync.aligned.m8n8.x2.shared.b16 {%0,%1}, [%2];"
                 : "=r"(r[0]), "=r"(r[1]) : "r"(addr));
}
__device__ __forceinline__ void mma16816(float* d, const uint32_t* a, const uint32_t* b) {
    asm volatile(
        "mma.sync.aligned.m16n8k16.row.col.f32.bf16.bf16.f32 "
        "{%0,%1,%2,%3}, {%4,%5,%6,%7}, {%8,%9}, {%0,%1,%2,%3};"
        : "+f"(d[0]), "+f"(d[1]), "+f"(d[2]), "+f"(d[3])
        : "r"(a[0]), "r"(a[1]), "r"(a[2]), "r"(a[3]), "r"(b[0]), "r"(b[1]));
}
__device__ __forceinline__ void mma16816h(float* d, const uint32_t* a, const uint32_t* b) {
    asm volatile(
        "mma.sync.aligned.m16n8k16.row.col.f32.f16.f16.f32 "
        "{%0,%1,%2,%3}, {%4,%5,%6,%7}, {%8,%9}, {%0,%1,%2,%3};"
        : "+f"(d[0]), "+f"(d[1]), "+f"(d[2]), "+f"(d[3])
        : "r"(a[0]), "r"(a[1]), "r"(a[2]), "r"(a[3]), "r"(b[0]), "r"(b[1]));
}

// ---------------- fused emb-gather + w_ih split (one launch) ------------------
__global__ __launch_bounds__(256)
void split_xw(const float* __restrict__ emb, const float* __restrict__ w_ih,
              __nv_bfloat16* __restrict__ Xh, __nv_bfloat16* __restrict__ Xl,
              __nv_bfloat16* __restrict__ Wh, __nv_bfloat16* __restrict__ Wl,
              const int* __restrict__ gather)
{
    int idx = blockIdx.x * 256 + threadIdx.x;
    const int ckpr = EE >> 3;
    const int nX = MM * ckpr;
    const float* src;
    __nv_bfloat16 *hi, *lo;
    int row, ck;
    if (idx < nX) {
        row = idx / ckpr; ck = idx - row * ckpr;
        int srow = (row < BB) ? gather[row] : gather[row - BB];
        src = emb + (size_t)srow * EE + ck * 8;
        hi = Xh; lo = Xl;
    } else {
        idx -= nX;
        if (idx >= GG * ckpr) return;
        row = idx / ckpr; ck = idx - row * ckpr;
        src = w_ih + (size_t)row * EE + ck * 8;
        hi = Wh; lo = Wl;
    }

    float4 v0 = ((const float4*)src)[0], v1 = ((const float4*)src)[1];
    float f[8] = {v0.x, v0.y, v0.z, v0.w, v1.x, v1.y, v1.z, v1.w};
    __nv_bfloat16 hb[8], lb[8];
#pragma unroll
    for (int i = 0; i < 8; i++) {
        hb[i] = __float2bfloat16(f[i]);
        lb[i] = __float2bfloat16(f[i] - __bfloat162float(hb[i]));
    }

    int nb = row >> 7, nr = row & 127;
    int kc = ck >> 3, chunk = ck & 7;
    size_t base = (((size_t)nb * (EE >> 6)) + kc) << 13;
    int dof = nr * 64 + ((chunk ^ (nr & 7)) << 3);
    *(uint4*)(hi + base + dof) = *(uint4*)hb;
    *(uint4*)(lo + base + dof) = *(uint4*)lb;
}

// ---------------- fp32 -> blocked/swizzled fp16 -------------------------------
__global__ __launch_bounds__(256)
void split_f16(const float* __restrict__ src, __half* __restrict__ dst,
               int rows, int K)
{
    int idx = blockIdx.x * 256 + threadIdx.x;
    int ck_per_row = K >> 3;
    if (idx >= rows * ck_per_row) return;
    int row = idx / ck_per_row;
    int ck  = idx - row * ck_per_row;

    const float4* s = (const float4*)(src + (size_t)row * K + ck * 8);
    float4 v0 = s[0], v1 = s[1];
    float f[8] = {v0.x, v0.y, v0.z, v0.w, v1.x, v1.y, v1.z, v1.w};
    __half h[8];
#pragma unroll
    for (int i = 0; i < 8; i++) h[i] = __float2half(f[i]);

    int nb = row >> 7, nr = row & 127;
    int kc = ck >> 3, chunk = ck & 7;
    size_t base = (((size_t)nb * (K >> 6)) + kc) << 13;
    int dof = nr * 64 + ((chunk ^ (nr & 7)) << 3);
    *(uint4*)(dst + base + dof) = *(uint4*)h;
}

// ---------------- barrier state init ------------------------------------------
__global__ void init_barrier() {
    int i = threadIdx.x;
    if (i < 8 * 32) g_grp[i] = 0;
    if (i == 0) { g_root = 0; g_flag = 0; }
}

// ---------------- bf16x3 GEMM (gx; unchanged, proven) --------------------------
#define TILEB 16384
#define STAGEB (4 * TILEB)
#define NSTAGE 3

__global__ __launch_bounds__(512, 1)
void bgemm_mma(const __nv_bfloat16* __restrict__ Ah, const __nv_bfloat16* __restrict__ Al,
               const __nv_bfloat16* __restrict__ Bh, const __nv_bfloat16* __restrict__ Bl,
               const float* __restrict__ bias, float* __restrict__ C,
               int N, int K)
{
    extern __shared__ char smraw[];
    const uint32_t base = (smem_u32(smraw) + 1023) & ~1023u;
    const uint32_t fullb  = base;
    const uint32_t emptyb = base + 24;
    const uint32_t tiles  = base + 1024;

    const int tid  = threadIdx.x;
    const int lane = tid & 31;
    const int wid  = tid >> 5;
    const int warp_m = wid >> 2;
    const int warp_n = wid & 3;
    const int nchunk = K >> 6;

    const size_t aBase = (size_t)blockIdx.x * nchunk;
    const size_t bBase = (size_t)blockIdx.y * nchunk;

    if (tid == 0) {
#pragma unroll
        for (int s = 0; s < NSTAGE; s++) {
            mbar_init(fullb + s * 8, 1);
            mbar_init(emptyb + s * 8, 512);
        }
        asm volatile("fence.proxy.async.shared::cta;" ::: "memory");
    }
    __syncthreads();

    auto load_stage = [&](int c) {
        const int s = c % NSTAGE;
        const uint32_t sb = tiles + (uint32_t)s * STAGEB;
        const uint32_t mb = fullb + s * 8;
        mbar_expect_tx(mb, STAGEB);
        bulk_cp(sb + 0 * TILEB, Ah + ((aBase + c) << 13), TILEB, mb);
        bulk_cp(sb + 1 * TILEB, Al + ((aBase + c) << 13), TILEB, mb);
        bulk_cp(sb + 2 * TILEB, Bh + ((bBase + c) << 13), TILEB, mb);
        bulk_cp(sb + 3 * TILEB, Bl + ((bBase + c) << 13), TILEB, mb);
    };

    if (tid == 0) { load_stage(0); if (nchunk > 1) load_stage(1); }

    float acc[2][4][4];
#pragma unroll
    for (int mt = 0; mt < 2; mt++)
#pragma unroll
        for (int nt = 0; nt < 4; nt++)
#pragma unroll
            for (int e = 0; e < 4; e++) acc[mt][nt][e] = 0.f;

    const int g = lane >> 3;
    const int r = lane & 7;

    uint32_t aoff[2][4], boff[2][4];
#pragma unroll
    for (int ks = 0; ks < 4; ks++) {
#pragma unroll
        for (int mt = 0; mt < 2; mt++) {
            int row = warp_m * 32 + mt * 16 + ((g & 1) << 3) + r;
            int ch  = 2 * ks + (g >> 1);
            aoff[mt][ks] = (uint32_t)(row * 128 + ((ch ^ (row & 7)) << 4));
        }
#pragma unroll
        for (int np = 0; np < 2; np++) {
            int row = warp_n * 32 + np * 16 + ((g >> 1) << 3) + r;
            int ch  = 2 * ks + (g & 1);
            boff[np][ks] = (uint32_t)(row * 128 + ((ch ^ (row & 7)) << 4));
        }
    }

    for (int c = 0; c < nchunk; c++) {
        const int s = c % NSTAGE;
        mbar_wait(fullb + s * 8, (c / NSTAGE) & 1);

        if (tid == 0 && c + 2 < nchunk) {
            const int c2 = c + 2, s2 = c2 % NSTAGE;
            if (c2 >= NSTAGE)
                mbar_wait(emptyb + s2 * 8, ((c2 - NSTAGE - s2) / NSTAGE) & 1);
            load_stage(c2);
        }

        const uint32_t sb = tiles + (uint32_t)s * STAGEB;
        const uint32_t tAh = sb, tAl = sb + TILEB, tBh = sb + 2 * TILEB, tBl = sb + 3 * TILEB;

#pragma unroll
        for (int ks = 0; ks < 4; ks++) {
            uint32_t ah[2][4], al[2][4];
#pragma unroll
            for (int mt = 0; mt < 2; mt++) {
                ldm_x4(ah[mt], tAh + aoff[mt][ks]);
                ldm_x4(al[mt], tAl + aoff[mt][ks]);
            }
            uint32_t bh[4][2], bl[4][2];
#pragma unroll
            for (int np = 0; np < 2; np++) {
                uint32_t t0[4], t1[4];
                ldm_x4(t0, tBh + boff[np][ks]);
                ldm_x4(t1, tBl + boff[np][ks]);
                bh[2 * np][0] = t0[0]; bh[2 * np][1] = t0[1];
                bh[2 * np + 1][0] = t0[2]; bh[2 * np + 1][1] = t0[3];
                bl[2 * np][0] = t1[0]; bl[2 * np][1] = t1[1];
                bl[2 * np + 1][0] = t1[2]; bl[2 * np + 1][1] = t1[3];
            }
#pragma unroll
            for (int mt = 0; mt < 2; mt++)
#pragma unroll
                for (int nt = 0; nt < 4; nt++)
                    mma16816(acc[mt][nt], ah[mt], bh[nt]);
#pragma unroll
            for (int mt = 0; mt < 2; mt++)
#pragma unroll
                for (int nt = 0; nt < 4; nt++)
                    mma16816(acc[mt][nt], ah[mt], bl[nt]);
#pragma unroll
            for (int mt = 0; mt < 2; mt++)
#pragma unroll
                for (int nt = 0; nt < 4; nt++)
                    mma16816(acc[mt][nt], al[mt], bh[nt]);
        }

        mbar_arrive(emptyb + s * 8);
    }

    const int bm = blockIdx.x * 128;
    const int bn = blockIdx.y * 128;
#pragma unroll
    for (int mt = 0; mt < 2; mt++) {
        int row0 = bm + warp_m * 32 + mt * 16 + (lane >> 2);
#pragma unroll
        for (int nt = 0; nt < 4; nt++) {
            int col = bn + warp_n * 32 + nt * 8 + ((lane & 3) << 1);
            float b0 = bias[col], b1 = bias[col + 1];
            float2 v0 = make_float2(acc[mt][nt][0] + b0, acc[mt][nt][1] + b1);
            float2 v1 = make_float2(acc[mt][nt][2] + b0, acc[mt][nt][3] + b1);
            *(float2*)(C + (size_t)row0 * N + col) = v0;
            *(float2*)(C + (size_t)(row0 + 8) * N + col) = v1;
        }
    }
}

// ---------------- fp16 GEMM, 128m x 256n tiles (logits; unchanged) -------------
#define STAGEH (3 * TILEB)               // 48 KB
#define NSTAGEH 4

__global__ __launch_bounds__(512, 1)
void hgemm_mma(const __half* __restrict__ A, const __half* __restrict__ B,
               const float* __restrict__ bias, float* __restrict__ C,
               int N, int K)
{
    extern __shared__ char smraw[];
    const uint32_t base = (smem_u32(smraw) + 1023) & ~1023u;
    const uint32_t fullb  = base;
    const uint32_t emptyb = base + 32;
    const uint32_t tiles  = base + 1024;

    const int tid  = threadIdx.x;
    const int lane = tid & 31;
    const int wid  = tid >> 5;
    const int warp_m = wid >> 2;
    const int warp_n = wid & 3;
    const int nchunk = K >> 6;

    const size_t aBase  = (size_t)blockIdx.x * nchunk;
    const size_t b0Base = (size_t)(blockIdx.y * 2) * nchunk;
    const size_t b1Base = (size_t)(blockIdx.y * 2 + 1) * nchunk;

    if (tid == 0) {
#pragma unroll
        for (int s = 0; s < NSTAGEH; s++) {
            mbar_init(fullb + s * 8, 1);
            mbar_init(emptyb + s * 8, 512);
        }
        asm volatile("fence.proxy.async.shared::cta;" ::: "memory");
    }
    __syncthreads();

    auto load_stage = [&](int c) {
        const int s = c % NSTAGEH;
        const uint32_t sb = tiles + (uint32_t)s * STAGEH;
        const uint32_t mb = fullb + s * 8;
        mbar_expect_tx(mb, STAGEH);
        bulk_cp(sb + 0 * TILEB, A + ((aBase + c) << 13), TILEB, mb);
        bulk_cp(sb + 1 * TILEB, B + ((b0Base + c) << 13), TILEB, mb);
        bulk_cp(sb + 2 * TILEB, B + ((b1Base + c) << 13), TILEB, mb);
    };

    if (tid == 0) {
        load_stage(0);
        if (nchunk > 1) load_stage(1);
        if (nchunk > 2) load_stage(2);
    }

    float acc[2][8][4];
#pragma unroll
    for (int mt = 0; mt < 2; mt++)
#pragma unroll
        for (int nt = 0; nt < 8; nt++)
#pragma unroll
            for (int e = 0; e < 4; e++) acc[mt][nt][e] = 0.f;

    const int g = lane >> 3;
    const int r = lane & 7;
    const uint32_t bsel = (warp_n >= 2) ? 2u * TILEB : 1u * TILEB;
    const int nbase = (warp_n & 1) * 64;

    uint32_t aoff[2][4], boff[4][4];
#pragma unroll
    for (int ks = 0; ks < 4; ks++) {
#pragma unroll
        for (int mt = 0; mt < 2; mt++) {
            int row = warp_m * 32 + mt * 16 + ((g & 1) << 3) + r;
            int ch  = 2 * ks + (g >> 1);
            aoff[mt][ks] = (uint32_t)(row * 128 + ((ch ^ (row & 7)) << 4));
        }
#pragma unroll
        for (int np = 0; np < 4; np++) {
            int row = nbase + np * 16 + ((g >> 1) << 3) + r;
            int ch  = 2 * ks + (g & 1);
            boff[np][ks] = (uint32_t)(row * 128 + ((ch ^ (row & 7)) << 4));
        }
    }

    for (int c = 0; c < nchunk; c++) {
        const int s = c % NSTAGEH;
        mbar_wait(fullb + s * 8, (c / NSTAGEH) & 1);

        if (tid == 0 && c + 3 < nchunk) {
            const int c2 = c + 3, s2 = c2 % NSTAGEH;
            if (c2 >= NSTAGEH)
                mbar_wait(emptyb + s2 * 8, ((c2 - NSTAGEH - s2) / NSTAGEH) & 1);
            load_stage(c2);
        }

        const uint32_t sb = tiles + (uint32_t)s * STAGEH;
        const uint32_t tA = sb, tB = sb + bsel;

#pragma unroll
        for (int ks = 0; ks < 4; ks++) {
            uint32_t aF[2][4];
#pragma unroll
            for (int mt = 0; mt < 2; mt++)
                ldm_x4(aF[mt], tA + aoff[mt][ks]);
            uint32_t bF[8][2];
#pragma unroll
            for (int np = 0; np < 4; np++) {
                uint32_t t0[4];
                ldm_x4(t0, tB + boff[np][ks]);
                bF[2 * np][0] = t0[0]; bF[2 * np][1] = t0[1];
                bF[2 * np + 1][0] = t0[2]; bF[2 * np + 1][1] = t0[3];
            }
#pragma unroll
            for (int mt = 0; mt < 2; mt++)
#pragma unroll
                for (int nt = 0; nt < 8; nt++)
                    mma16816h(acc[mt][nt], aF[mt], bF[nt]);
        }

        mbar_arrive(emptyb + s * 8);
    }

    const int bm = blockIdx.x * 128;
    const int bn = blockIdx.y * 256;
#pragma unroll
    for (int mt = 0; mt < 2; mt++) {
        int row0 = bm + warp_m * 32 + mt * 16 + (lane >> 2);
#pragma unroll
        for (int nt = 0; nt < 8; nt++) {
            int col = bn + warp_n * 64 + nt * 8 + ((lane & 3) << 1);
            float b0 = bias[col], b1 = bias[col + 1];
            float2 v0 = make_float2(acc[mt][nt][0] + b0, acc[mt][nt][1] + b1);
            float2 v1 = make_float2(acc[mt][nt][2] + b0, acc[mt][nt][3] + b1);
            *(float2*)(C + (size_t)row0 * N + col) = v0;
            *(float2*)(C + (size_t)(row0 + 8) * N + col) = v1;
        }
    }
}

// ---------------- persistent GRU: tensor-core dots, tree barrier ---------------
#define SM_WH 0
#define SM_WL 49152
#define SM_AH 98304
#define SM_AL 163840
#define SM_HLOC 229376
#define GRU_SMEM 230400

__global__ __launch_bounds__(512, 1)
void gru_persistent(const float* __restrict__ w_hh,
                    const float* __restrict__ b_hh,
                    const float* __restrict__ gx,
                    __half* __restrict__ Fa,
                    float* __restrict__ hidden)
{
    extern __shared__ char smem[];
    __shared__ uint64_t h_mbar_store[2];
    const uint32_t sb   = smem_u32(smem);
    const uint32_t tWh  = sb + SM_WH;
    const uint32_t tWl  = sb + SM_WL;
    const uint32_t tAh  = sb + SM_AH;
    const uint32_t tAl  = sb + SM_AL;
    float* hloc    = (float*)(smem + SM_HLOC);
    float* scratch = (float*)(smem + SM_AH);       // aliases Ah (24 KB used)
    const uint32_t hmbH = smem_u32(&h_mbar_store[0]);
    const uint32_t hmbL = smem_u32(&h_mbar_store[1]);

    const int tid = threadIdx.x;
    const int c = blockIdx.x;

    if (tid == 0) {
        mbar_init(hmbH, 1);
        mbar_init(hmbL, 1);
        asm volatile("fence.proxy.async.shared::cta;" ::: "memory");
    }

    // one-time: W (24 x 1024) -> smem bf16 hi/lo, blocked/swizzled
    for (int i = tid; i < 24 * 256; i += 512) {
        int n = i >> 8;
        int k = (i & 255) * 4;
        int gate = n >> 3, uu = n & 7;
        float4 v = *(const float4*)(w_hh + ((size_t)(gate * HH + c * 8 + uu)) * HH + k);
        float f[4] = {v.x, v.y, v.z, v.w};
        __nv_bfloat16 hb[4], lb[4];
#pragma unroll
        for (int q = 0; q < 4; q++) {
            hb[q] = __float2bfloat16(f[q]);
            lb[q] = __float2bfloat16(f[q] - __bfloat162float(hb[q]));
        }
        int kc = k >> 6, e = k & 63, ch = e >> 3;
        uint32_t off = kc * 3072 + n * 128 + ((ch ^ (n & 7)) << 4) + (e & 7) * 2;
        *(uint2*)(smem + SM_WH + off) = *(uint2*)hb;
        *(uint2*)(smem + SM_WL + off) = *(uint2*)lb;
    }
    for (int i = tid; i < (65536 * 2) / 16; i += 512)
        *(uint4*)(smem + SM_AH + i * 16) = make_uint4(0, 0, 0, 0);
    for (int i = tid; i < 256; i += 512) hloc[i] = 0.f;
    __syncthreads();

    const int warp = tid >> 5, lane = tid & 31;
    const int mt = warp & 1, kq = warp >> 1;
    const int g = lane >> 3, r = lane & 7;
    const int ln = lane & 15, r2 = ln & 7, half2 = ln >> 3;

    uint32_t aoff[4], boff4[4], boff2[4];
#pragma unroll
    for (int ks = 0; ks < 4; ks++) {
        int rowa = mt * 16 + ((g & 1) << 3) + r;
        int cha  = 2 * ks + (g >> 1);
        aoff[ks]  = (uint32_t)(rowa * 128 + ((cha ^ (rowa & 7)) << 4));
        int rowb = ((g >> 1) << 3) + r;
        int chb  = 2 * ks + (g & 1);
        boff4[ks] = (uint32_t)(rowb * 128 + ((chb ^ (rowb & 7)) << 4));
        int rowb2 = 16 + r2;
        int chb2  = 2 * ks + half2;
        boff2[ks] = (uint32_t)(rowb2 * 128 + ((chb2 ^ (rowb2 & 7)) << 4));
    }

    const int uu = tid >> 5, bb = tid & 31;
    const bool pw = (tid < 256);
    float bh3[3];
    if (pw) {
#pragma unroll
        for (int gg = 0; gg < 3; gg++)
            bh3[gg] = b_hh[gg * HH + c * 8 + uu];
    }
    const int mtb = bb >> 4;
    const int lsrc = (bb & 7) * 4 + (uu >> 1);
    const int epos = 2 * ((bb & 15) >> 3) + (uu & 1);
    const int j = c * 8 + uu;
    const int kcj = j >> 6, chj = (j >> 3) & 7, ej = j & 7;
    const int hoff = kcj * 2048 + bb * 64 + ((chj ^ (bb & 7)) << 3) + ej;
    const int kc_f = j >> 6, ch_f = (j >> 3) & 7, je_f = j & 7;

    int hph = 0;

    for (int t = 0; t < TT; t++) {
        float pgx[3];
        if (pw) {
            const float* gxp = gx + ((size_t)t * BB + bb) * GG;
            pgx[0] = gxp[j];
            pgx[1] = gxp[HH + j];
            pgx[2] = gxp[2 * HH + j];
        }

        float acc[3][4];
#pragma unroll
        for (int nt = 0; nt < 3; nt++)
#pragma unroll
            for (int e = 0; e < 4; e++) acc[nt][e] = 0.f;

        // ---- half-1: needs only Ah (hi) ----
        if (t > 0) mbar_wait(hmbH, hph);
#pragma unroll
        for (int s = 0; s < 8; s++) {
            const int kc = kq * 2 + (s >> 2);
            const int ks = s & 3;
            const uint32_t ab = (uint32_t)(kc * 4096);
            const uint32_t wb = (uint32_t)(kc * 3072);
            uint32_t ah[4];
            ldm_x4(ah, tAh + ab + aoff[ks]);
            uint32_t bhf[3][2], blf[3][2];
            {
                uint32_t t0[4], t1[4];
                ldm_x4(t0, tWh + wb + boff4[ks]);
                ldm_x4(t1, tWl + wb + boff4[ks]);
                bhf[0][0] = t0[0]; bhf[0][1] = t0[1];
                bhf[1][0] = t0[2]; bhf[1][1] = t0[3];
                blf[0][0] = t1[0]; blf[0][1] = t1[1];
                blf[1][0] = t1[2]; blf[1][1] = t1[3];
                ldm_x2(bhf[2], tWh + wb + boff2[ks]);
                ldm_x2(blf[2], tWl + wb + boff2[ks]);
            }
#pragma unroll
            for (int nt = 0; nt < 3; nt++) mma16816(acc[nt], ah, bhf[nt]);
#pragma unroll
            for (int nt = 0; nt < 3; nt++) mma16816(acc[nt], ah, blf[nt]);
        }

        // ---- half-2: needs Al (lo) ----
        if (t > 0) { mbar_wait(hmbL, hph); hph ^= 1; }
#pragma unroll
        for (int s = 0; s < 8; s++) {
            const int kc = kq * 2 + (s >> 2);
            const int ks = s & 3;
            const uint32_t ab = (uint32_t)(kc * 4096);
            const uint32_t wb = (uint32_t)(kc * 3072);
            uint32_t al[4];
            ldm_x4(al, tAl + ab + aoff[ks]);
            uint32_t bhf[3][2];
            {
                uint32_t t0[4];
                ldm_x4(t0, tWh + wb + boff4[ks]);
                bhf[0][0] = t0[0]; bhf[0][1] = t0[1];
                bhf[1][0] = t0[2]; bhf[1][1] = t0[3];
                ldm_x2(bhf[2], tWh + wb + boff2[ks]);
            }
#pragma unroll
            for (int nt = 0; nt < 3; nt++) mma16816(acc[nt], al, bhf[nt]);
        }

        __syncthreads();                      // all MMA reads of Ah/Al done
        {
            float* sp = &scratch[warp * 384 + lane * 12];
#pragma unroll
            for (int nt = 0; nt < 3; nt++)
                *(float4*)(sp + nt * 4) = *(float4*)acc[nt];
        }
        __syncthreads();

        if (pw) {
            float gh[3];
#pragma unroll
            for (int nt = 0; nt < 3; nt++) {
                float s0 = 0.f;
#pragma unroll
                for (int kq2 = 0; kq2 < 8; kq2++)
                    s0 += scratch[(kq2 * 2 + mtb) * 384 + lsrc * 12 + nt * 4 + epos];
                gh[nt] = s0 + bh3[nt];
            }
            float hold = hloc[uu * 32 + bb];
            float rr = 1.f / (1.f + expf(-(pgx[0] + gh[0])));
            float zz = 1.f / (1.f + expf(-(pgx[1] + gh[1])));
            float nn = tanhf(pgx[2] + rr * gh[2]);
            float hnew = (1.f - zz) * nn + zz * hold;

            hloc[uu * 32 + bb] = hnew;

            {
                int row = t * BB + bb;
                int nb = row >> 7, nr = row & 127;
                size_t basef = (((size_t)nb * (HH >> 6)) + kc_f) << 13;
                Fa[basef + nr * 64 + ((ch_f ^ (nr & 7)) << 3) + je_f] = __float2half(hnew);
            }
            {
                __nv_bfloat16 hb = __float2bfloat16(hnew);
                __nv_bfloat16 lb = __float2bfloat16(hnew - __bfloat162float(hb));
                g_hBh[(t + 1) & 1][hoff] = hb;
                g_hBl[(t + 1) & 1][hoff] = lb;
            }
            if (t == TT - 1) hidden[bb * HH + j] = hnew;
            __threadfence();
        }
        __syncthreads();

        if (t < TT - 1 && tid == 0) {
            // two-level tree barrier: 8 group counters (128B-strided lines),
            // group-last -> root, root-last -> release flag. Monotonic.
            unsigned o = atomicAdd(&g_grp[(c & 7) * 32], 1u);
            if ((o & 15) == 15) {                       // 16th arrival in group
                unsigned rt = atomicAdd(&g_root, 1u);
                if ((rt & 7) == 7)                      // 8th group this step
                    atomicAdd(&g_flag, 1u);             // release step t
            }
            unsigned target = (unsigned)(t + 1);
            while (ld_acq(&g_flag) < target) {}
            mbar_expect_tx(hmbH, 65536);
            bulk_cp(tAh, &g_hBh[(t + 1) & 1][0], 65536, hmbH);
            mbar_expect_tx(hmbL, 65536);
            bulk_cp(tAl, &g_hBl[(t + 1) & 1][0], 65536, hmbL);
        }
    }
}

// ---------------- launch -------------------------------------------------------
extern "C" void kernel_launch(void* const* d_in, const int* in_sizes, int n_in,
                              void* d_out, int out_size)
{
    const int*   inputs = (const int*)  d_in[0];
    const float* emb    = (const float*)d_in[3];
    const float* w_ih   = (const float*)d_in[4];
    const float* w_hh   = (const float*)d_in[5];
    const float* b_ih   = (const float*)d_in[6];
    const float* b_hh   = (const float*)d_in[7];
    const float* out_w  = (const float*)d_in[8];
    const float* out_b  = (const float*)d_in[9];

    float* logits = (float*)d_out;
    float* hidden = (float*)d_out + (size_t)MM * VV;

    float* gx;   cudaGetSymbolAddress((void**)&gx,   g_gx);
    __nv_bfloat16 *Xh, *Xl, *Wh, *Wl;
    __half *Fw, *Fa;
    cudaGetSymbolAddress((void**)&Xh, g_Xh);
    cudaGetSymbolAddress((void**)&Xl, g_Xl);
    cudaGetSymbolAddress((void**)&Wh, g_Wh);
    cudaGetSymbolAddress((void**)&Wl, g_Wl);
    cudaGetSymbolAddress((void**)&Fw, g_Fw);
    cudaGetSymbolAddress((void**)&Fa, g_Fa);

    const int bgemm_smem = 1024 + NSTAGE * STAGEB + 1024;
    cudaFuncSetAttribute(bgemm_mma, cudaFuncAttributeMaxDynamicSharedMemorySize, bgemm_smem);
    const int hgemm_smem = 1024 + NSTAGEH * STAGEH + 1024;
    cudaFuncSetAttribute(hgemm_mma, cudaFuncAttributeMaxDynamicSharedMemorySize, hgemm_smem);
    cudaFuncSetAttribute(gru_persistent, cudaFuncAttributeMaxDynamicSharedMemorySize, GRU_SMEM);

    // 0: fused emb-gather + w_ih split
    {
        int total = (MM + GG) * (EE / 8);
        split_xw<<<(total + 255) / 256, 256>>>(emb, w_ih, Xh, Xl, Wh, Wl, inputs);
    }

    // 1: gx = X @ w_ih^T + b_ih (bf16x3)
    {
        dim3 grid(MM / 128, GG / 128);
        bgemm_mma<<<grid, 512, bgemm_smem>>>(Xh, Xl, Wh, Wl, b_ih, gx, GG, EE);
    }

    // 2: barrier state init
    init_barrier<<<1, 256>>>();

    // 3: GRU recurrence (tensor-core dots; tree grid barrier)
    gru_persistent<<<NCTA, 512, GRU_SMEM>>>(w_hh, b_hh, gx, Fa, hidden);

    // 4: out_w -> fp16 blocked
    split_f16<<<(VV * (HH / 8) + 255) / 256, 256>>>(out_w, Fw, VV, HH);

    // 5: logits = hall @ out_w^T + out_b (fp16, 128x256 tiles)
    {
        dim3 grid(MM / 128, VV / 256);   // (32, 125)
        hgemm_mma<<<grid, 512, hgemm_smem>>>(Fa, Fw, out_b, logits, VV, HH);
    }
}

// round 16
// speedup vs baseline: 1.1119x; 1.1119x over previous
#include <cuda_runtime.h>
#include <cuda_bf16.h>
#include <cuda_fp16.h>
#include <math.h>
#include <stdint.h>

// Problem dims
#define TT 128
#define BB 32
#define EE 512
#define HH 1024
#define VV 32000
#define GG (3 * HH)       // 3072
#define MM (TT * BB)      // 4096
#define NCTA 128

// ---------------- scratch (device globals) ----------------------------------
__device__ float g_gx[MM * GG];
__device__ __nv_bfloat16 g_hBh[2][BB * HH];    // ping-pong h, bf16 hi, blocked
__device__ __nv_bfloat16 g_hBl[2][BB * HH];    // bf16 lo
__device__ unsigned g_cnt = 0;                  // flat monotonic grid barrier
__device__ __half g_Xf[MM * EE];               // gathered emb rows, fp16 blocked
__device__ __half g_Wf[GG * EE];               // w_ih, fp16 blocked
__device__ __half g_Fw[VV * HH];               // out_w fp16 blocked
__device__ __half g_Fa[MM * HH];               // hall fp16 blocked (GRU output)

// ---------------- helpers ----------------------------------------------------
__device__ __forceinline__ uint32_t smem_u32(const void* p) {
    uint32_t a;
    asm("{ .reg .u64 t; cvta.to.shared.u64 t, %1; cvt.u32.u64 %0, t; }"
        : "=r"(a) : "l"(p));
    return a;
}
__device__ __forceinline__ unsigned ld_acq(unsigned* p) {
    unsigned v;
    asm volatile("ld.acquire.gpu.u32 %0, [%1];" : "=r"(v) : "l"(p) : "memory");
    return v;
}
__device__ __forceinline__ void mbar_init(uint32_t mbar, int cnt) {
    asm volatile("mbarrier.init.shared.b64 [%0], %1;" :: "r"(mbar), "r"(cnt) : "memory");
}
__device__ __forceinline__ void mbar_expect_tx(uint32_t mbar, uint32_t bytes) {
    asm volatile("mbarrier.arrive.expect_tx.shared.b64 _, [%0], %1;"
                 :: "r"(mbar), "r"(bytes) : "memory");
}
__device__ __forceinline__ void mbar_arrive(uint32_t mbar) {
    asm volatile("mbarrier.arrive.shared.b64 _, [%0];" :: "r"(mbar) : "memory");
}
__device__ __forceinline__ void bulk_cp(uint32_t dst, const void* src, uint32_t bytes,
                                        uint32_t mbar) {
    asm volatile(
        "cp.async.bulk.shared::cluster.global.mbarrier::complete_tx::bytes "
        "[%0], [%1], %2, [%3];"
        :: "r"(dst), "l"(src), "r"(bytes), "r"(mbar) : "memory");
}
__device__ __forceinline__ void mbar_wait(uint32_t mbar, int ph) {
    asm volatile(
        "{\n\t.reg .pred P1;\n"
        "WL%=:\n\t"
        "mbarrier.try_wait.parity.acquire.cta.shared::cta.b64 P1, [%0], %1, 0x989680;\n\t"
        "@P1 bra.uni WD%=;\n\t"
        "bra.uni WL%=;\n"
        "WD%=:\n\t}"
        :: "r"(mbar), "r"(ph) : "memory");
}
__device__ __forceinline__ void ldm_x4(uint32_t* r, uint32_t addr) {
    asm volatile("ldmatrix.sync.aligned.m8n8.x4.shared.b16 {%0,%1,%2,%3}, [%4];"
                 : "=r"(r[0]), "=r"(r[1]), "=r"(r[2]), "=r"(r[3]) : "r"(addr));
}
__device__ __forceinline__ void ldm_x2(uint32_t* r, uint32_t addr) {
    asm volatile("ldmatrix.sync.aligned.m8n8.x2.shared.b16 {%0,%1}, [%2];"
                 : "=r"(r[0]), "=r"(r[1]) : "r"(addr));
}
__device__ __forceinline__ void mma16816(float* d, const uint32_t* a, const uint32_t* b) {
    asm volatile(
        "mma.sync.aligned.m16n8k16.row.col.f32.bf16.bf16.f32 "
        "{%0,%1,%2,%3}, {%4,%5,%6,%7}, {%8,%9}, {%0,%1,%2,%3};"
        : "+f"(d[0]), "+f"(d[1]), "+f"(d[2]), "+f"(d[3])
        : "r"(a[0]), "r"(a[1]), "r"(a[2]), "r"(a[3]), "r"(b[0]), "r"(b[1]));
}
__device__ __forceinline__ void mma16816h(float* d, const uint32_t* a, const uint32_t* b) {
    asm volatile(
        "mma.sync.aligned.m16n8k16.row.col.f32.f16.f16.f32 "
        "{%0,%1,%2,%3}, {%4,%5,%6,%7}, {%8,%9}, {%0,%1,%2,%3};"
        : "+f"(d[0]), "+f"(d[1]), "+f"(d[2]), "+f"(d[3])
        : "r"(a[0]), "r"(a[1]), "r"(a[2]), "r"(a[3]), "r"(b[0]), "r"(b[1]));
}

// ---------------- fused emb-gather + w_ih -> fp16 blocked ----------------------
__global__ __launch_bounds__(256)
void split_xwf(const float* __restrict__ emb, const float* __restrict__ w_ih,
               __half* __restrict__ Xf, __half* __restrict__ Wf,
               const int* __restrict__ gather)
{
    int idx = blockIdx.x * 256 + threadIdx.x;
    const int ckpr = EE >> 3;
    const int nX = MM * ckpr;
    const float* src;
    __half* dst;
    int row, ck;
    if (idx < nX) {
        row = idx / ckpr; ck = idx - row * ckpr;
        int srow = (row < BB) ? gather[row] : gather[row - BB];
        src = emb + (size_t)srow * EE + ck * 8;
        dst = Xf;
    } else {
        idx -= nX;
        if (idx >= GG * ckpr) return;
        row = idx / ckpr; ck = idx - row * ckpr;
        src = w_ih + (size_t)row * EE + ck * 8;
        dst = Wf;
    }

    float4 v0 = ((const float4*)src)[0], v1 = ((const float4*)src)[1];
    float f[8] = {v0.x, v0.y, v0.z, v0.w, v1.x, v1.y, v1.z, v1.w};
    __half h[8];
#pragma unroll
    for (int i = 0; i < 8; i++) h[i] = __float2half(f[i]);

    int nb = row >> 7, nr = row & 127;
    int kc = ck >> 3, chunk = ck & 7;
    size_t base = (((size_t)nb * (EE >> 6)) + kc) << 13;
    int dof = nr * 64 + ((chunk ^ (nr & 7)) << 3);
    *(uint4*)(dst + base + dof) = *(uint4*)h;
}

// ---------------- fp32 -> blocked/swizzled fp16 (out_w) ------------------------
__global__ __launch_bounds__(256)
void split_f16(const float* __restrict__ src, __half* __restrict__ dst,
               int rows, int K)
{
    int idx = blockIdx.x * 256 + threadIdx.x;
    int ck_per_row = K >> 3;
    if (idx >= rows * ck_per_row) return;
    int row = idx / ck_per_row;
    int ck  = idx - row * ck_per_row;

    const float4* s = (const float4*)(src + (size_t)row * K + ck * 8);
    float4 v0 = s[0], v1 = s[1];
    float f[8] = {v0.x, v0.y, v0.z, v0.w, v1.x, v1.y, v1.z, v1.w};
    __half h[8];
#pragma unroll
    for (int i = 0; i < 8; i++) h[i] = __float2half(f[i]);

    int nb = row >> 7, nr = row & 127;
    int kc = ck >> 3, chunk = ck & 7;
    size_t base = (((size_t)nb * (K >> 6)) + kc) << 13;
    int dof = nr * 64 + ((chunk ^ (nr & 7)) << 3);
    *(uint4*)(dst + base + dof) = *(uint4*)h;
}

// ---------------- barrier state init ------------------------------------------
__global__ void init_barrier() {
    if (threadIdx.x == 0) g_cnt = 0;
}

// ---------------- fp16 GEMM, 128m x 256n tiles (gx AND logits) -----------------
#define TILEB 16384
#define STAGEH (3 * TILEB)               // 48 KB
#define NSTAGEH 4

__global__ __launch_bounds__(512, 1)
void hgemm_mma(const __half* __restrict__ A, const __half* __restrict__ B,
               const float* __restrict__ bias, float* __restrict__ C,
               int N, int K)
{
    extern __shared__ char smraw[];
    const uint32_t base = (smem_u32(smraw) + 1023) & ~1023u;
    const uint32_t fullb  = base;
    const uint32_t emptyb = base + 32;
    const uint32_t tiles  = base + 1024;

    const int tid  = threadIdx.x;
    const int lane = tid & 31;
    const int wid  = tid >> 5;
    const int warp_m = wid >> 2;
    const int warp_n = wid & 3;
    const int nchunk = K >> 6;

    const size_t aBase  = (size_t)blockIdx.x * nchunk;
    const size_t b0Base = (size_t)(blockIdx.y * 2) * nchunk;
    const size_t b1Base = (size_t)(blockIdx.y * 2 + 1) * nchunk;

    if (tid == 0) {
#pragma unroll
        for (int s = 0; s < NSTAGEH; s++) {
            mbar_init(fullb + s * 8, 1);
            mbar_init(emptyb + s * 8, 512);
        }
        asm volatile("fence.proxy.async.shared::cta;" ::: "memory");
    }
    __syncthreads();

    auto load_stage = [&](int c) {
        const int s = c % NSTAGEH;
        const uint32_t sb = tiles + (uint32_t)s * STAGEH;
        const uint32_t mb = fullb + s * 8;
        mbar_expect_tx(mb, STAGEH);
        bulk_cp(sb + 0 * TILEB, A + ((aBase + c) << 13), TILEB, mb);
        bulk_cp(sb + 1 * TILEB, B + ((b0Base + c) << 13), TILEB, mb);
        bulk_cp(sb + 2 * TILEB, B + ((b1Base + c) << 13), TILEB, mb);
    };

    if (tid == 0) {
        load_stage(0);
        if (nchunk > 1) load_stage(1);
        if (nchunk > 2) load_stage(2);
    }

    float acc[2][8][4];
#pragma unroll
    for (int mt = 0; mt < 2; mt++)
#pragma unroll
        for (int nt = 0; nt < 8; nt++)
#pragma unroll
            for (int e = 0; e < 4; e++) acc[mt][nt][e] = 0.f;

    const int g = lane >> 3;
    const int r = lane & 7;
    const uint32_t bsel = (warp_n >= 2) ? 2u * TILEB : 1u * TILEB;
    const int nbase = (warp_n & 1) * 64;

    uint32_t aoff[2][4], boff[4][4];
#pragma unroll
    for (int ks = 0; ks < 4; ks++) {
#pragma unroll
        for (int mt = 0; mt < 2; mt++) {
            int row = warp_m * 32 + mt * 16 + ((g & 1) << 3) + r;
            int ch  = 2 * ks + (g >> 1);
            aoff[mt][ks] = (uint32_t)(row * 128 + ((ch ^ (row & 7)) << 4));
        }
#pragma unroll
        for (int np = 0; np < 4; np++) {
            int row = nbase + np * 16 + ((g >> 1) << 3) + r;
            int ch  = 2 * ks + (g & 1);
            boff[np][ks] = (uint32_t)(row * 128 + ((ch ^ (row & 7)) << 4));
        }
    }

    for (int c = 0; c < nchunk; c++) {
        const int s = c % NSTAGEH;
        mbar_wait(fullb + s * 8, (c / NSTAGEH) & 1);

        if (tid == 0 && c + 3 < nchunk) {
            const int c2 = c + 3, s2 = c2 % NSTAGEH;
            if (c2 >= NSTAGEH)
                mbar_wait(emptyb + s2 * 8, ((c2 - NSTAGEH - s2) / NSTAGEH) & 1);
            load_stage(c2);
        }

        const uint32_t sb = tiles + (uint32_t)s * STAGEH;
        const uint32_t tA = sb, tB = sb + bsel;

#pragma unroll
        for (int ks = 0; ks < 4; ks++) {
            uint32_t aF[2][4];
#pragma unroll
            for (int mt = 0; mt < 2; mt++)
                ldm_x4(aF[mt], tA + aoff[mt][ks]);
            uint32_t bF[8][2];
#pragma unroll
            for (int np = 0; np < 4; np++) {
                uint32_t t0[4];
                ldm_x4(t0, tB + boff[np][ks]);
                bF[2 * np][0] = t0[0]; bF[2 * np][1] = t0[1];
                bF[2 * np + 1][0] = t0[2]; bF[2 * np + 1][1] = t0[3];
            }
#pragma unroll
            for (int mt = 0; mt < 2; mt++)
#pragma unroll
                for (int nt = 0; nt < 8; nt++)
                    mma16816h(acc[mt][nt], aF[mt], bF[nt]);
        }

        mbar_arrive(emptyb + s * 8);
    }

    const int bm = blockIdx.x * 128;
    const int bn = blockIdx.y * 256;
#pragma unroll
    for (int mt = 0; mt < 2; mt++) {
        int row0 = bm + warp_m * 32 + mt * 16 + (lane >> 2);
#pragma unroll
        for (int nt = 0; nt < 8; nt++) {
            int col = bn + warp_n * 64 + nt * 8 + ((lane & 3) << 1);
            float b0 = bias[col], b1 = bias[col + 1];
            float2 v0 = make_float2(acc[mt][nt][0] + b0, acc[mt][nt][1] + b1);
            float2 v1 = make_float2(acc[mt][nt][2] + b0, acc[mt][nt][3] + b1);
            *(float2*)(C + (size_t)row0 * N + col) = v0;
            *(float2*)(C + (size_t)(row0 + 8) * N + col) = v1;
        }
    }
}

// ---------------- persistent GRU: tensor-core dots (R14 proven version) --------
#define SM_WH 0
#define SM_WL 49152
#define SM_AH 98304
#define SM_AL 163840
#define SM_HLOC 229376
#define GRU_SMEM 230400

__global__ __launch_bounds__(512, 1)
void gru_persistent(const float* __restrict__ w_hh,
                    const float* __restrict__ b_hh,
                    const float* __restrict__ gx,
                    __half* __restrict__ Fa,
                    float* __restrict__ hidden)
{
    extern __shared__ char smem[];
    __shared__ uint64_t h_mbar_store[2];
    const uint32_t sb   = smem_u32(smem);
    const uint32_t tWh  = sb + SM_WH;
    const uint32_t tWl  = sb + SM_WL;
    const uint32_t tAh  = sb + SM_AH;
    const uint32_t tAl  = sb + SM_AL;
    float* hloc    = (float*)(smem + SM_HLOC);
    float* scratch = (float*)(smem + SM_AH);       // aliases Ah (24 KB used)
    const uint32_t hmbH = smem_u32(&h_mbar_store[0]);
    const uint32_t hmbL = smem_u32(&h_mbar_store[1]);

    const int tid = threadIdx.x;
    const int c = blockIdx.x;

    if (tid == 0) {
        mbar_init(hmbH, 1);
        mbar_init(hmbL, 1);
        asm volatile("fence.proxy.async.shared::cta;" ::: "memory");
    }

    // one-time: W (24 x 1024) -> smem bf16 hi/lo, blocked/swizzled
    for (int i = tid; i < 24 * 256; i += 512) {
        int n = i >> 8;
        int k = (i & 255) * 4;
        int gate = n >> 3, uu = n & 7;
        float4 v = *(const float4*)(w_hh + ((size_t)(gate * HH + c * 8 + uu)) * HH + k);
        float f[4] = {v.x, v.y, v.z, v.w};
        __nv_bfloat16 hb[4], lb[4];
#pragma unroll
        for (int q = 0; q < 4; q++) {
            hb[q] = __float2bfloat16(f[q]);
            lb[q] = __float2bfloat16(f[q] - __bfloat162float(hb[q]));
        }
        int kc = k >> 6, e = k & 63, ch = e >> 3;
        uint32_t off = kc * 3072 + n * 128 + ((ch ^ (n & 7)) << 4) + (e & 7) * 2;
        *(uint2*)(smem + SM_WH + off) = *(uint2*)hb;
        *(uint2*)(smem + SM_WL + off) = *(uint2*)lb;
    }
    for (int i = tid; i < (65536 * 2) / 16; i += 512)
        *(uint4*)(smem + SM_AH + i * 16) = make_uint4(0, 0, 0, 0);
    for (int i = tid; i < 256; i += 512) hloc[i] = 0.f;
    __syncthreads();

    const int warp = tid >> 5, lane = tid & 31;
    const int mt = warp & 1, kq = warp >> 1;
    const int g = lane >> 3, r = lane & 7;
    const int ln = lane & 15, r2 = ln & 7, half2 = ln >> 3;

    uint32_t aoff[4], boff4[4], boff2[4];
#pragma unroll
    for (int ks = 0; ks < 4; ks++) {
        int rowa = mt * 16 + ((g & 1) << 3) + r;
        int cha  = 2 * ks + (g >> 1);
        aoff[ks]  = (uint32_t)(rowa * 128 + ((cha ^ (rowa & 7)) << 4));
        int rowb = ((g >> 1) << 3) + r;
        int chb  = 2 * ks + (g & 1);
        boff4[ks] = (uint32_t)(rowb * 128 + ((chb ^ (rowb & 7)) << 4));
        int rowb2 = 16 + r2;
        int chb2  = 2 * ks + half2;
        boff2[ks] = (uint32_t)(rowb2 * 128 + ((chb2 ^ (rowb2 & 7)) << 4));
    }

    const int uu = tid >> 5, bb = tid & 31;
    const bool pw = (tid < 256);
    float bh3[3];
    if (pw) {
#pragma unroll
        for (int gg = 0; gg < 3; gg++)
            bh3[gg] = b_hh[gg * HH + c * 8 + uu];
    }
    const int mtb = bb >> 4;
    const int lsrc = (bb & 7) * 4 + (uu >> 1);
    const int epos = 2 * ((bb & 15) >> 3) + (uu & 1);
    const int j = c * 8 + uu;
    const int kcj = j >> 6, chj = (j >> 3) & 7, ej = j & 7;
    const int hoff = kcj * 2048 + bb * 64 + ((chj ^ (bb & 7)) << 3) + ej;
    const int kc_f = j >> 6, ch_f = (j >> 3) & 7, je_f = j & 7;

    int hph = 0;

    for (int t = 0; t < TT; t++) {
        float pgx[3];
        if (pw) {
            const float* gxp = gx + ((size_t)t * BB + bb) * GG;
            pgx[0] = gxp[j];
            pgx[1] = gxp[HH + j];
            pgx[2] = gxp[2 * HH + j];
        }

        float acc[3][4];
#pragma unroll
        for (int nt = 0; nt < 3; nt++)
#pragma unroll
            for (int e = 0; e < 4; e++) acc[nt][e] = 0.f;

        // ---- half-1: needs only Ah (hi) ----
        if (t > 0) mbar_wait(hmbH, hph);
#pragma unroll
        for (int s = 0; s < 8; s++) {
            const int kc = kq * 2 + (s >> 2);
            const int ks = s & 3;
            const uint32_t ab = (uint32_t)(kc * 4096);
            const uint32_t wb = (uint32_t)(kc * 3072);
            uint32_t ah[4];
            ldm_x4(ah, tAh + ab + aoff[ks]);
            uint32_t bhf[3][2], blf[3][2];
            {
                uint32_t t0[4], t1[4];
                ldm_x4(t0, tWh + wb + boff4[ks]);
                ldm_x4(t1, tWl + wb + boff4[ks]);
                bhf[0][0] = t0[0]; bhf[0][1] = t0[1];
                bhf[1][0] = t0[2]; bhf[1][1] = t0[3];
                blf[0][0] = t1[0]; blf[0][1] = t1[1];
                blf[1][0] = t1[2]; blf[1][1] = t1[3];
                ldm_x2(bhf[2], tWh + wb + boff2[ks]);
                ldm_x2(blf[2], tWl + wb + boff2[ks]);
            }
#pragma unroll
            for (int nt = 0; nt < 3; nt++) mma16816(acc[nt], ah, bhf[nt]);
#pragma unroll
            for (int nt = 0; nt < 3; nt++) mma16816(acc[nt], ah, blf[nt]);
        }

        // ---- half-2: needs Al (lo) ----
        if (t > 0) { mbar_wait(hmbL, hph); hph ^= 1; }
#pragma unroll
        for (int s = 0; s < 8; s++) {
            const int kc = kq * 2 + (s >> 2);
            const int ks = s & 3;
            const uint32_t ab = (uint32_t)(kc * 4096);
            const uint32_t wb = (uint32_t)(kc * 3072);
            uint32_t al[4];
            ldm_x4(al, tAl + ab + aoff[ks]);
            uint32_t bhf[3][2];
            {
                uint32_t t0[4];
                ldm_x4(t0, tWh + wb + boff4[ks]);
                bhf[0][0] = t0[0]; bhf[0][1] = t0[1];
                bhf[1][0] = t0[2]; bhf[1][1] = t0[3];
                ldm_x2(bhf[2], tWh + wb + boff2[ks]);
            }
#pragma unroll
            for (int nt = 0; nt < 3; nt++) mma16816(acc[nt], al, bhf[nt]);
        }

        __syncthreads();                      // all MMA reads of Ah/Al done
        {
            float* sp = &scratch[warp * 384 + lane * 12];
#pragma unroll
            for (int nt = 0; nt < 3; nt++)
                *(float4*)(sp + nt * 4) = *(float4*)acc[nt];
        }
        __syncthreads();

        if (pw) {
            float gh[3];
#pragma unroll
            for (int nt = 0; nt < 3; nt++) {
                float s0 = 0.f;
#pragma unroll
                for (int kq2 = 0; kq2 < 8; kq2++)
                    s0 += scratch[(kq2 * 2 + mtb) * 384 + lsrc * 12 + nt * 4 + epos];
                gh[nt] = s0 + bh3[nt];
            }
            float hold = hloc[uu * 32 + bb];
            float rr = 1.f / (1.f + expf(-(pgx[0] + gh[0])));
            float zz = 1.f / (1.f + expf(-(pgx[1] + gh[1])));
            float nn = tanhf(pgx[2] + rr * gh[2]);
            float hnew = (1.f - zz) * nn + zz * hold;

            hloc[uu * 32 + bb] = hnew;

            {
                int row = t * BB + bb;
                int nb = row >> 7, nr = row & 127;
                size_t basef = (((size_t)nb * (HH >> 6)) + kc_f) << 13;
                Fa[basef + nr * 64 + ((ch_f ^ (nr & 7)) << 3) + je_f] = __float2half(hnew);
            }
            {
                __nv_bfloat16 hb = __float2bfloat16(hnew);
                __nv_bfloat16 lb = __float2bfloat16(hnew - __bfloat162float(hb));
                g_hBh[(t + 1) & 1][hoff] = hb;
                g_hBl[(t + 1) & 1][hoff] = lb;
            }
            if (t == TT - 1) hidden[bb * HH + j] = hnew;
        }
        __syncthreads();

        if (t < TT - 1 && tid == 0) {
            // flat monotonic grid barrier (R14 proven); tid0-only fence makes
            // this CTA's pw stores (ordered by the syncthreads above) globally
            // visible before the arrival -- standard CG grid-sync pattern.
            __threadfence();
            atomicAdd(&g_cnt, 1u);
            unsigned target = (unsigned)(t + 1) * NCTA;
            while (ld_acq(&g_cnt) < target) {}
            mbar_expect_tx(hmbH, 65536);
            bulk_cp(tAh, &g_hBh[(t + 1) & 1][0], 65536, hmbH);
            mbar_expect_tx(hmbL, 65536);
            bulk_cp(tAl, &g_hBl[(t + 1) & 1][0], 65536, hmbL);
        }
    }
}

// ---------------- launch -------------------------------------------------------
extern "C" void kernel_launch(void* const* d_in, const int* in_sizes, int n_in,
                              void* d_out, int out_size)
{
    const int*   inputs = (const int*)  d_in[0];
    const float* emb    = (const float*)d_in[3];
    const float* w_ih   = (const float*)d_in[4];
    const float* w_hh   = (const float*)d_in[5];
    const float* b_ih   = (const float*)d_in[6];
    const float* b_hh   = (const float*)d_in[7];
    const float* out_w  = (const float*)d_in[8];
    const float* out_b  = (const float*)d_in[9];

    float* logits = (float*)d_out;
    float* hidden = (float*)d_out + (size_t)MM * VV;

    float* gx;   cudaGetSymbolAddress((void**)&gx, g_gx);
    __half *Xf, *Wf, *Fw, *Fa;
    cudaGetSymbolAddress((void**)&Xf, g_Xf);
    cudaGetSymbolAddress((void**)&Wf, g_Wf);
    cudaGetSymbolAddress((void**)&Fw, g_Fw);
    cudaGetSymbolAddress((void**)&Fa, g_Fa);

    const int hgemm_smem = 1024 + NSTAGEH * STAGEH + 1024;
    cudaFuncSetAttribute(hgemm_mma, cudaFuncAttributeMaxDynamicSharedMemorySize, hgemm_smem);
    cudaFuncSetAttribute(gru_persistent, cudaFuncAttributeMaxDynamicSharedMemorySize, GRU_SMEM);

    // 0: fused emb-gather + w_ih -> fp16 blocked
    {
        int total = (MM + GG) * (EE / 8);
        split_xwf<<<(total + 255) / 256, 256>>>(emb, w_ih, Xf, Wf, inputs);
    }

    // 1: gx = X @ w_ih^T + b_ih (fp16 single-product, 128x256 tiles)
    {
        dim3 grid(MM / 128, GG / 256);   // (32, 12)
        hgemm_mma<<<grid, 512, hgemm_smem>>>(Xf, Wf, b_ih, gx, GG, EE);
    }

    // 2: barrier state init
    init_barrier<<<1, 32>>>();

    // 3: GRU recurrence (tensor-core bf16x3 dots; flat barrier)
    gru_persistent<<<NCTA, 512, GRU_SMEM>>>(w_hh, b_hh, gx, Fa, hidden);

    // 4: out_w -> fp16 blocked
    split_f16<<<(VV * (HH / 8) + 255) / 256, 256>>>(out_w, Fw, VV, HH);

    // 5: logits = hall @ out_w^T + out_b (fp16, 128x256 tiles)
    {
        dim3 grid(MM / 128, VV / 256);   // (32, 125)
        hgemm_mma<<<grid, 512, hgemm_smem>>>(Fa, Fw, out_b, logits, VV, HH);
    }
}

// round 17
// speedup vs baseline: 1.1504x; 1.0346x over previous
#include <cuda_runtime.h>
#include <cuda_bf16.h>
#include <cuda_fp16.h>
#include <math.h>
#include <stdint.h>

// Problem dims
#define TT 128
#define BB 32
#define EE 512
#define HH 1024
#define VV 32000
#define GG (3 * HH)       // 3072
#define MM (TT * BB)      // 4096
#define NCTA 128

// ---------------- scratch (device globals) ----------------------------------
__device__ float g_gx[MM * GG];
__device__ __nv_bfloat16 g_hBh[2][BB * HH];    // ping-pong h, bf16 hi, blocked
__device__ __nv_bfloat16 g_hBl[2][BB * HH];    // bf16 lo
__device__ unsigned g_cnt = 0;                  // flat monotonic grid barrier
__device__ __half g_Xf[MM * EE];               // gathered emb rows, fp16 blocked
__device__ __half g_Wf[GG * EE];               // w_ih, fp16 blocked
__device__ __half g_Fw[VV * HH];               // out_w fp16 blocked (built in GRU)
__device__ __half g_Fa[MM * HH];               // hall fp16 blocked (GRU output)

// ---------------- helpers ----------------------------------------------------
__device__ __forceinline__ uint32_t smem_u32(const void* p) {
    uint32_t a;
    asm("{ .reg .u64 t; cvta.to.shared.u64 t, %1; cvt.u32.u64 %0, t; }"
        : "=r"(a) : "l"(p));
    return a;
}
__device__ __forceinline__ unsigned ld_acq(unsigned* p) {
    unsigned v;
    asm volatile("ld.acquire.gpu.u32 %0, [%1];" : "=r"(v) : "l"(p) : "memory");
    return v;
}
__device__ __forceinline__ void mbar_init(uint32_t mbar, int cnt) {
    asm volatile("mbarrier.init.shared.b64 [%0], %1;" :: "r"(mbar), "r"(cnt) : "memory");
}
__device__ __forceinline__ void mbar_expect_tx(uint32_t mbar, uint32_t bytes) {
    asm volatile("mbarrier.arrive.expect_tx.shared.b64 _, [%0], %1;"
                 :: "r"(mbar), "r"(bytes) : "memory");
}
__device__ __forceinline__ void mbar_arrive(uint32_t mbar) {
    asm volatile("mbarrier.arrive.shared.b64 _, [%0];" :: "r"(mbar) : "memory");
}
__device__ __forceinline__ void bulk_cp(uint32_t dst, const void* src, uint32_t bytes,
                                        uint32_t mbar) {
    asm volatile(
        "cp.async.bulk.shared::cluster.global.mbarrier::complete_tx::bytes "
        "[%0], [%1], %2, [%3];"
        :: "r"(dst), "l"(src), "r"(bytes), "r"(mbar) : "memory");
}
__device__ __forceinline__ void mbar_wait(uint32_t mbar, int ph) {
    asm volatile(
        "{\n\t.reg .pred P1;\n"
        "WL%=:\n\t"
        "mbarrier.try_wait.parity.acquire.cta.shared::cta.b64 P1, [%0], %1, 0x989680;\n\t"
        "@P1 bra.uni WD%=;\n\t"
        "bra.uni WL%=;\n"
        "WD%=:\n\t}"
        :: "r"(mbar), "r"(ph) : "memory");
}
__device__ __forceinline__ void ldm_x4(uint32_t* r, uint32_t addr) {
    asm volatile("ldmatrix.sync.aligned.m8n8.x4.shared.b16 {%0,%1,%2,%3}, [%4];"
                 : "=r"(r[0]), "=r"(r[1]), "=r"(r[2]), "=r"(r[3]) : "r"(addr));
}
__device__ __forceinline__ void ldm_x2(uint32_t* r, uint32_t addr) {
    asm volatile("ldmatrix.sync.aligned.m8n8.x2.shared.b16 {%0,%1}, [%2];"
                 : "=r"(r[0]), "=r"(r[1]) : "r"(addr));
}
__device__ __forceinline__ void mma16816(float* d, const uint32_t* a, const uint32_t* b) {
    asm volatile(
        "mma.sync.aligned.m16n8k16.row.col.f32.bf16.bf16.f32 "
        "{%0,%1,%2,%3}, {%4,%5,%6,%7}, {%8,%9}, {%0,%1,%2,%3};"
        : "+f"(d[0]), "+f"(d[1]), "+f"(d[2]), "+f"(d[3])
        : "r"(a[0]), "r"(a[1]), "r"(a[2]), "r"(a[3]), "r"(b[0]), "r"(b[1]));
}
__device__ __forceinline__ void mma16816h(float* d, const uint32_t* a, const uint32_t* b) {
    asm volatile(
        "mma.sync.aligned.m16n8k16.row.col.f32.f16.f16.f32 "
        "{%0,%1,%2,%3}, {%4,%5,%6,%7}, {%8,%9}, {%0,%1,%2,%3};"
        : "+f"(d[0]), "+f"(d[1]), "+f"(d[2]), "+f"(d[3])
        : "r"(a[0]), "r"(a[1]), "r"(a[2]), "r"(a[3]), "r"(b[0]), "r"(b[1]));
}

// ---------------- fused emb-gather + w_ih -> fp16 blocked ----------------------
__global__ __launch_bounds__(256)
void split_xwf(const float* __restrict__ emb, const float* __restrict__ w_ih,
               __half* __restrict__ Xf, __half* __restrict__ Wf,
               const int* __restrict__ gather)
{
    int idx = blockIdx.x * 256 + threadIdx.x;
    const int ckpr = EE >> 3;
    const int nX = MM * ckpr;
    const float* src;
    __half* dst;
    int row, ck;
    if (idx < nX) {
        row = idx / ckpr; ck = idx - row * ckpr;
        int srow = (row < BB) ? gather[row] : gather[row - BB];
        src = emb + (size_t)srow * EE + ck * 8;
        dst = Xf;
    } else {
        idx -= nX;
        if (idx >= GG * ckpr) return;
        row = idx / ckpr; ck = idx - row * ckpr;
        src = w_ih + (size_t)row * EE + ck * 8;
        dst = Wf;
    }

    float4 v0 = ((const float4*)src)[0], v1 = ((const float4*)src)[1];
    float f[8] = {v0.x, v0.y, v0.z, v0.w, v1.x, v1.y, v1.z, v1.w};
    __half h[8];
#pragma unroll
    for (int i = 0; i < 8; i++) h[i] = __float2half(f[i]);

    int nb = row >> 7, nr = row & 127;
    int kc = ck >> 3, chunk = ck & 7;
    size_t base = (((size_t)nb * (EE >> 6)) + kc) << 13;
    int dof = nr * 64 + ((chunk ^ (nr & 7)) << 3);
    *(uint4*)(dst + base + dof) = *(uint4*)h;
}

// ---------------- barrier state init ------------------------------------------
__global__ void init_barrier() {
    if (threadIdx.x == 0) g_cnt = 0;
}

// ---------------- fp16 GEMM, 128m x 256n tiles (gx AND logits) -----------------
#define TILEB 16384
#define STAGEH (3 * TILEB)               // 48 KB
#define NSTAGEH 4

__global__ __launch_bounds__(512, 1)
void hgemm_mma(const __half* __restrict__ A, const __half* __restrict__ B,
               const float* __restrict__ bias, float* __restrict__ C,
               int N, int K)
{
    extern __shared__ char smraw[];
    const uint32_t base = (smem_u32(smraw) + 1023) & ~1023u;
    const uint32_t fullb  = base;
    const uint32_t emptyb = base + 32;
    const uint32_t tiles  = base + 1024;

    const int tid  = threadIdx.x;
    const int lane = tid & 31;
    const int wid  = tid >> 5;
    const int warp_m = wid >> 2;
    const int warp_n = wid & 3;
    const int nchunk = K >> 6;

    const size_t aBase  = (size_t)blockIdx.x * nchunk;
    const size_t b0Base = (size_t)(blockIdx.y * 2) * nchunk;
    const size_t b1Base = (size_t)(blockIdx.y * 2 + 1) * nchunk;

    if (tid == 0) {
#pragma unroll
        for (int s = 0; s < NSTAGEH; s++) {
            mbar_init(fullb + s * 8, 1);
            mbar_init(emptyb + s * 8, 512);
        }
        asm volatile("fence.proxy.async.shared::cta;" ::: "memory");
    }
    __syncthreads();

    auto load_stage = [&](int c) {
        const int s = c % NSTAGEH;
        const uint32_t sb = tiles + (uint32_t)s * STAGEH;
        const uint32_t mb = fullb + s * 8;
        mbar_expect_tx(mb, STAGEH);
        bulk_cp(sb + 0 * TILEB, A + ((aBase + c) << 13), TILEB, mb);
        bulk_cp(sb + 1 * TILEB, B + ((b0Base + c) << 13), TILEB, mb);
        bulk_cp(sb + 2 * TILEB, B + ((b1Base + c) << 13), TILEB, mb);
    };

    if (tid == 0) {
        load_stage(0);
        if (nchunk > 1) load_stage(1);
        if (nchunk > 2) load_stage(2);
    }

    float acc[2][8][4];
#pragma unroll
    for (int mt = 0; mt < 2; mt++)
#pragma unroll
        for (int nt = 0; nt < 8; nt++)
#pragma unroll
            for (int e = 0; e < 4; e++) acc[mt][nt][e] = 0.f;

    const int g = lane >> 3;
    const int r = lane & 7;
    const uint32_t bsel = (warp_n >= 2) ? 2u * TILEB : 1u * TILEB;
    const int nbase = (warp_n & 1) * 64;

    uint32_t aoff[2][4], boff[4][4];
#pragma unroll
    for (int ks = 0; ks < 4; ks++) {
#pragma unroll
        for (int mt = 0; mt < 2; mt++) {
            int row = warp_m * 32 + mt * 16 + ((g & 1) << 3) + r;
            int ch  = 2 * ks + (g >> 1);
            aoff[mt][ks] = (uint32_t)(row * 128 + ((ch ^ (row & 7)) << 4));
        }
#pragma unroll
        for (int np = 0; np < 4; np++) {
            int row = nbase + np * 16 + ((g >> 1) << 3) + r;
            int ch  = 2 * ks + (g & 1);
            boff[np][ks] = (uint32_t)(row * 128 + ((ch ^ (row & 7)) << 4));
        }
    }

    for (int c = 0; c < nchunk; c++) {
        const int s = c % NSTAGEH;
        mbar_wait(fullb + s * 8, (c / NSTAGEH) & 1);

        if (tid == 0 && c + 3 < nchunk) {
            const int c2 = c + 3, s2 = c2 % NSTAGEH;
            if (c2 >= NSTAGEH)
                mbar_wait(emptyb + s2 * 8, ((c2 - NSTAGEH - s2) / NSTAGEH) & 1);
            load_stage(c2);
        }

        const uint32_t sb = tiles + (uint32_t)s * STAGEH;
        const uint32_t tA = sb, tB = sb + bsel;

#pragma unroll
        for (int ks = 0; ks < 4; ks++) {
            uint32_t aF[2][4];
#pragma unroll
            for (int mt = 0; mt < 2; mt++)
                ldm_x4(aF[mt], tA + aoff[mt][ks]);
            uint32_t bF[8][2];
#pragma unroll
            for (int np = 0; np < 4; np++) {
                uint32_t t0[4];
                ldm_x4(t0, tB + boff[np][ks]);
                bF[2 * np][0] = t0[0]; bF[2 * np][1] = t0[1];
                bF[2 * np + 1][0] = t0[2]; bF[2 * np + 1][1] = t0[3];
            }
#pragma unroll
            for (int mt = 0; mt < 2; mt++)
#pragma unroll
                for (int nt = 0; nt < 8; nt++)
                    mma16816h(acc[mt][nt], aF[mt], bF[nt]);
        }

        mbar_arrive(emptyb + s * 8);
    }

    const int bm = blockIdx.x * 128;
    const int bn = blockIdx.y * 256;
#pragma unroll
    for (int mt = 0; mt < 2; mt++) {
        int row0 = bm + warp_m * 32 + mt * 16 + (lane >> 2);
#pragma unroll
        for (int nt = 0; nt < 8; nt++) {
            int col = bn + warp_n * 64 + nt * 8 + ((lane & 3) << 1);
            float b0 = bias[col], b1 = bias[col + 1];
            float2 v0 = make_float2(acc[mt][nt][0] + b0, acc[mt][nt][1] + b1);
            float2 v1 = make_float2(acc[mt][nt][2] + b0, acc[mt][nt][3] + b1);
            *(float2*)(C + (size_t)row0 * N + col) = v0;
            *(float2*)(C + (size_t)(row0 + 8) * N + col) = v1;
        }
    }
}

// ---------------- persistent GRU: tc dots + chunked h copy + fused out_w cvt ---
#define SM_WH 0
#define SM_WL 49152
#define SM_AH 98304
#define SM_AL 163840
#define SM_HLOC 229376
#define GRU_SMEM 230400

__global__ __launch_bounds__(512, 1)
void gru_persistent(const float* __restrict__ w_hh,
                    const float* __restrict__ b_hh,
                    const float* __restrict__ gx,
                    __half* __restrict__ Fa,
                    float* __restrict__ hidden,
                    const float* __restrict__ out_w,
                    __half* __restrict__ Fw)
{
    extern __shared__ char smem[];
    __shared__ uint64_t h_mbar_store[8];          // hi[0..3], lo[0..3]
    const uint32_t sb   = smem_u32(smem);
    const uint32_t tWh  = sb + SM_WH;
    const uint32_t tWl  = sb + SM_WL;
    const uint32_t tAh  = sb + SM_AH;
    const uint32_t tAl  = sb + SM_AL;
    float* hloc    = (float*)(smem + SM_HLOC);
    float* scratch = (float*)(smem + SM_AH);       // aliases Ah (24 KB used)

    const int tid = threadIdx.x;
    const int c = blockIdx.x;

    if (tid == 0) {
#pragma unroll
        for (int q = 0; q < 8; q++)
            mbar_init(smem_u32(&h_mbar_store[q]), 1);
        asm volatile("fence.proxy.async.shared::cta;" ::: "memory");
    }

    // one-time: W (24 x 1024) -> smem bf16 hi/lo, blocked/swizzled
    for (int i = tid; i < 24 * 256; i += 512) {
        int n = i >> 8;
        int k = (i & 255) * 4;
        int gate = n >> 3, uu = n & 7;
        float4 v = *(const float4*)(w_hh + ((size_t)(gate * HH + c * 8 + uu)) * HH + k);
        float f[4] = {v.x, v.y, v.z, v.w};
        __nv_bfloat16 hb[4], lb[4];
#pragma unroll
        for (int q = 0; q < 4; q++) {
            hb[q] = __float2bfloat16(f[q]);
            lb[q] = __float2bfloat16(f[q] - __bfloat162float(hb[q]));
        }
        int kc = k >> 6, e = k & 63, ch = e >> 3;
        uint32_t off = kc * 3072 + n * 128 + ((ch ^ (n & 7)) << 4) + (e & 7) * 2;
        *(uint2*)(smem + SM_WH + off) = *(uint2*)hb;
        *(uint2*)(smem + SM_WL + off) = *(uint2*)lb;
    }
    for (int i = tid; i < (65536 * 2) / 16; i += 512)
        *(uint4*)(smem + SM_AH + i * 16) = make_uint4(0, 0, 0, 0);
    for (int i = tid; i < 256; i += 512) hloc[i] = 0.f;
    __syncthreads();

    const int warp = tid >> 5, lane = tid & 31;
    const int mt = warp & 1, kq = warp >> 1;
    const int g = lane >> 3, r = lane & 7;
    const int ln = lane & 15, r2 = ln & 7, half2 = ln >> 3;
    const uint32_t myHi = smem_u32(&h_mbar_store[kq >> 1]);
    const uint32_t myLo = smem_u32(&h_mbar_store[4 + (kq >> 1)]);

    uint32_t aoff[4], boff4[4], boff2[4];
#pragma unroll
    for (int ks = 0; ks < 4; ks++) {
        int rowa = mt * 16 + ((g & 1) << 3) + r;
        int cha  = 2 * ks + (g >> 1);
        aoff[ks]  = (uint32_t)(rowa * 128 + ((cha ^ (rowa & 7)) << 4));
        int rowb = ((g >> 1) << 3) + r;
        int chb  = 2 * ks + (g & 1);
        boff4[ks] = (uint32_t)(rowb * 128 + ((chb ^ (rowb & 7)) << 4));
        int rowb2 = 16 + r2;
        int chb2  = 2 * ks + half2;
        boff2[ks] = (uint32_t)(rowb2 * 128 + ((chb2 ^ (rowb2 & 7)) << 4));
    }

    const int uu = tid >> 5, bb = tid & 31;
    const bool pw = (tid < 256);
    float bh3[3];
    if (pw) {
#pragma unroll
        for (int gg = 0; gg < 3; gg++)
            bh3[gg] = b_hh[gg * HH + c * 8 + uu];
    }
    const int mtb = bb >> 4;
    const int lsrc = (bb & 7) * 4 + (uu >> 1);
    const int epos = 2 * ((bb & 15) >> 3) + (uu & 1);
    const int j = c * 8 + uu;
    const int kcj = j >> 6, chj = (j >> 3) & 7, ej = j & 7;
    const int hoff = kcj * 2048 + bb * 64 + ((chj ^ (bb & 7)) << 3) + ej;
    const int kc_f = j >> 6, ch_f = (j >> 3) & 7, je_f = j & 7;

    int hph = 0;

    for (int t = 0; t < TT; t++) {
        // ---- fused out_w -> fp16 blocked conversion (idle warps, t<64) ----
        // These warps (kq 4-7) wait on the LAST h-copy chunks anyway, so the
        // DRAM load latency of this conversion hides under their mbar wait.
        if (!pw && t < 64) {
            size_t u0 = (((size_t)t * NCTA + c) << 9) + (size_t)(tid - 256) * 2;
#pragma unroll
            for (int q = 0; q < 2; q++) {
                size_t u = u0 + q;
                if (u < (size_t)VV * HH / 8) {
                    int row = (int)(u >> 7);
                    int ck  = (int)(u & 127);
                    const float4* s4 = (const float4*)(out_w + (size_t)row * HH + ck * 8);
                    float4 v0 = s4[0], v1 = s4[1];
                    __half h8[8];
                    h8[0] = __float2half(v0.x); h8[1] = __float2half(v0.y);
                    h8[2] = __float2half(v0.z); h8[3] = __float2half(v0.w);
                    h8[4] = __float2half(v1.x); h8[5] = __float2half(v1.y);
                    h8[6] = __float2half(v1.z); h8[7] = __float2half(v1.w);
                    int nb = row >> 7, nr = row & 127;
                    int kc2 = ck >> 3, chunk2 = ck & 7;
                    size_t basef = (((size_t)nb * (HH >> 6)) + kc2) << 13;
                    int dof = nr * 64 + ((chunk2 ^ (nr & 7)) << 3);
                    *(uint4*)(Fw + basef + dof) = *(uint4*)h8;
                }
            }
        }

        float pgx[3];
        if (pw) {
            const float* gxp = gx + ((size_t)t * BB + bb) * GG;
            pgx[0] = gxp[j];
            pgx[1] = gxp[HH + j];
            pgx[2] = gxp[2 * HH + j];
        }

        float acc[3][4];
#pragma unroll
        for (int nt = 0; nt < 3; nt++)
#pragma unroll
            for (int e = 0; e < 4; e++) acc[nt][e] = 0.f;

        // ---- half-1: needs only this warp's hi chunk ----
        if (t > 0) mbar_wait(myHi, hph);
#pragma unroll
        for (int s = 0; s < 8; s++) {
            const int kc = kq * 2 + (s >> 2);
            const int ks = s & 3;
            const uint32_t ab = (uint32_t)(kc * 4096);
            const uint32_t wb = (uint32_t)(kc * 3072);
            uint32_t ah[4];
            ldm_x4(ah, tAh + ab + aoff[ks]);
            uint32_t bhf[3][2], blf[3][2];
            {
                uint32_t t0[4], t1[4];
                ldm_x4(t0, tWh + wb + boff4[ks]);
                ldm_x4(t1, tWl + wb + boff4[ks]);
                bhf[0][0] = t0[0]; bhf[0][1] = t0[1];
                bhf[1][0] = t0[2]; bhf[1][1] = t0[3];
                blf[0][0] = t1[0]; blf[0][1] = t1[1];
                blf[1][0] = t1[2]; blf[1][1] = t1[3];
                ldm_x2(bhf[2], tWh + wb + boff2[ks]);
                ldm_x2(blf[2], tWl + wb + boff2[ks]);
            }
#pragma unroll
            for (int nt = 0; nt < 3; nt++) mma16816(acc[nt], ah, bhf[nt]);
#pragma unroll
            for (int nt = 0; nt < 3; nt++) mma16816(acc[nt], ah, blf[nt]);
        }

        // ---- half-2: needs this warp's lo chunk ----
        if (t > 0) { mbar_wait(myLo, hph); hph ^= 1; }
#pragma unroll
        for (int s = 0; s < 8; s++) {
            const int kc = kq * 2 + (s >> 2);
            const int ks = s & 3;
            const uint32_t ab = (uint32_t)(kc * 4096);
            const uint32_t wb = (uint32_t)(kc * 3072);
            uint32_t al[4];
            ldm_x4(al, tAl + ab + aoff[ks]);
            uint32_t bhf[3][2];
            {
                uint32_t t0[4];
                ldm_x4(t0, tWh + wb + boff4[ks]);
                bhf[0][0] = t0[0]; bhf[0][1] = t0[1];
                bhf[1][0] = t0[2]; bhf[1][1] = t0[3];
                ldm_x2(bhf[2], tWh + wb + boff2[ks]);
            }
#pragma unroll
            for (int nt = 0; nt < 3; nt++) mma16816(acc[nt], al, bhf[nt]);
        }

        __syncthreads();                      // all MMA reads of Ah/Al done
        {
            float* sp = &scratch[warp * 384 + lane * 12];
#pragma unroll
            for (int nt = 0; nt < 3; nt++)
                *(float4*)(sp + nt * 4) = *(float4*)acc[nt];
        }
        __syncthreads();

        if (pw) {
            float gh[3];
#pragma unroll
            for (int nt = 0; nt < 3; nt++) {
                float s0 = 0.f;
#pragma unroll
                for (int kq2 = 0; kq2 < 8; kq2++)
                    s0 += scratch[(kq2 * 2 + mtb) * 384 + lsrc * 12 + nt * 4 + epos];
                gh[nt] = s0 + bh3[nt];
            }
            float hold = hloc[uu * 32 + bb];
            float rr = 1.f / (1.f + expf(-(pgx[0] + gh[0])));
            float zz = 1.f / (1.f + expf(-(pgx[1] + gh[1])));
            float nn = tanhf(pgx[2] + rr * gh[2]);
            float hnew = (1.f - zz) * nn + zz * hold;

            hloc[uu * 32 + bb] = hnew;

            {
                int row = t * BB + bb;
                int nb = row >> 7, nr = row & 127;
                size_t basef = (((size_t)nb * (HH >> 6)) + kc_f) << 13;
                Fa[basef + nr * 64 + ((ch_f ^ (nr & 7)) << 3) + je_f] = __float2half(hnew);
            }
            {
                __nv_bfloat16 hb = __float2bfloat16(hnew);
                __nv_bfloat16 lb = __float2bfloat16(hnew - __bfloat162float(hb));
                g_hBh[(t + 1) & 1][hoff] = hb;
                g_hBl[(t + 1) & 1][hoff] = lb;
            }
            if (t == TT - 1) hidden[bb * HH + j] = hnew;
        }
        __syncthreads();

        if (t < TT - 1 && tid == 0) {
            // flat monotonic grid barrier (proven) + chunked copy issue
            __threadfence();
            atomicAdd(&g_cnt, 1u);
            unsigned target = (unsigned)(t + 1) * NCTA;
            while (ld_acq(&g_cnt) < target) {}
            const char* srcH = (const char*)&g_hBh[(t + 1) & 1][0];
            const char* srcL = (const char*)&g_hBl[(t + 1) & 1][0];
#pragma unroll
            for (int q = 0; q < 4; q++) {
                uint32_t mb = smem_u32(&h_mbar_store[q]);
                mbar_expect_tx(mb, 16384);
                bulk_cp(tAh + q * 16384, srcH + q * 16384, 16384, mb);
            }
#pragma unroll
            for (int q = 0; q < 4; q++) {
                uint32_t mb = smem_u32(&h_mbar_store[4 + q]);
                mbar_expect_tx(mb, 16384);
                bulk_cp(tAl + q * 16384, srcL + q * 16384, 16384, mb);
            }
        }
    }
}

// ---------------- launch -------------------------------------------------------
extern "C" void kernel_launch(void* const* d_in, const int* in_sizes, int n_in,
                              void* d_out, int out_size)
{
    const int*   inputs = (const int*)  d_in[0];
    const float* emb    = (const float*)d_in[3];
    const float* w_ih   = (const float*)d_in[4];
    const float* w_hh   = (const float*)d_in[5];
    const float* b_ih   = (const float*)d_in[6];
    const float* b_hh   = (const float*)d_in[7];
    const float* out_w  = (const float*)d_in[8];
    const float* out_b  = (const float*)d_in[9];

    float* logits = (float*)d_out;
    float* hidden = (float*)d_out + (size_t)MM * VV;

    float* gx;   cudaGetSymbolAddress((void**)&gx, g_gx);
    __half *Xf, *Wf, *Fw, *Fa;
    cudaGetSymbolAddress((void**)&Xf, g_Xf);
    cudaGetSymbolAddress((void**)&Wf, g_Wf);
    cudaGetSymbolAddress((void**)&Fw, g_Fw);
    cudaGetSymbolAddress((void**)&Fa, g_Fa);

    const int hgemm_smem = 1024 + NSTAGEH * STAGEH + 1024;
    cudaFuncSetAttribute(hgemm_mma, cudaFuncAttributeMaxDynamicSharedMemorySize, hgemm_smem);
    cudaFuncSetAttribute(gru_persistent, cudaFuncAttributeMaxDynamicSharedMemorySize, GRU_SMEM);

    // 0: fused emb-gather + w_ih -> fp16 blocked
    {
        int total = (MM + GG) * (EE / 8);
        split_xwf<<<(total + 255) / 256, 256>>>(emb, w_ih, Xf, Wf, inputs);
    }

    // 1: gx = X @ w_ih^T + b_ih (fp16 single-product, 128x256 tiles)
    {
        dim3 grid(MM / 128, GG / 256);   // (32, 12)
        hgemm_mma<<<grid, 512, hgemm_smem>>>(Xf, Wf, b_ih, gx, GG, EE);
    }

    // 2: barrier state init
    init_barrier<<<1, 32>>>();

    // 3: GRU recurrence (tensor-core bf16x3 dots; chunked h copy;
    //    out_w->fp16 conversion fused into idle warps)
    gru_persistent<<<NCTA, 512, GRU_SMEM>>>(w_hh, b_hh, gx, Fa, hidden, out_w, Fw);

    // 4: logits = hall @ out_w^T + out_b (fp16, 128x256 tiles)
    {
        dim3 grid(MM / 128, VV / 256);   // (32, 125)
        hgemm_mma<<<grid, 512, hgemm_smem>>>(Fa, Fw, out_b, logits, VV, HH);
    }
}